// round 14
// baseline (speedup 1.0000x reference)
#include <cuda_runtime.h>
#include <cuda_bf16.h>
#include <math.h>
#include <stdint.h>

// Problem constants
#define B_    8
#define S_    64
#define T_    512
#define HID_  4096
#define NH_   32
#define NKV_  32
#define D_    128
#define HIST_ 2048
#define BSZ_  64
#define NBLK_ 33
#define L_    2112
#define QKVW  12288   // 3 * HID_

__device__ float g_qkv[(size_t)T_ * QKVW];
__device__ float g_attn[(size_t)T_ * HID_];
// Pre-converted activation tiles: 4 mblk x 128 chunks x 16KB (hi 8K | lo 8K)
__device__ __align__(16) char g_xt[(size_t)8388608];

// ==================================================================
// Helpers
// ==================================================================
__device__ __forceinline__ uint32_t smem_u32(const void* p) {
    return (uint32_t)__cvta_generic_to_shared(p);
}
__device__ __forceinline__ uint32_t pack_bf2(float x0, float x1) {
    uint32_t d;
    asm("cvt.rn.bf16x2.f32 %0, %1, %2;" : "=r"(d) : "f"(x1), "f"(x0));
    return d;
}
__device__ __forceinline__ float2 unpack_bf2(uint32_t u) {
    float2 r;
    r.x = __uint_as_float(u << 16);
    r.y = __uint_as_float(u & 0xffff0000u);
    return r;
}
__device__ __forceinline__ void split4(float4 v, uint32_t* hi, uint32_t* lo) {
    uint32_t h0 = pack_bf2(v.x, v.y);
    uint32_t h1 = pack_bf2(v.z, v.w);
    float2 f0 = unpack_bf2(h0), f1 = unpack_bf2(h1);
    hi[0] = h0; hi[1] = h1;
    lo[0] = pack_bf2(v.x - f0.x, v.y - f0.y);
    lo[1] = pack_bf2(v.z - f1.x, v.w - f1.y);
}
__device__ __forceinline__ void ldsm4(uint32_t* r, uint32_t addr) {
    asm volatile("ldmatrix.sync.aligned.m8n8.x4.shared.b16 {%0,%1,%2,%3}, [%4];"
                 : "=r"(r[0]), "=r"(r[1]), "=r"(r[2]), "=r"(r[3]) : "r"(addr));
}
__device__ __forceinline__ void ldsm4t(uint32_t* r, uint32_t addr) {
    asm volatile("ldmatrix.sync.aligned.m8n8.x4.trans.shared.b16 {%0,%1,%2,%3}, [%4];"
                 : "=r"(r[0]), "=r"(r[1]), "=r"(r[2]), "=r"(r[3]) : "r"(addr));
}
__device__ __forceinline__ void mma16816(float* d, const uint32_t* a, const uint32_t* b) {
    asm("mma.sync.aligned.m16n8k16.row.col.f32.bf16.bf16.f32 "
        "{%0,%1,%2,%3}, {%4,%5,%6,%7}, {%8,%9}, {%0,%1,%2,%3};"
        : "+f"(d[0]), "+f"(d[1]), "+f"(d[2]), "+f"(d[3])
        : "r"(a[0]), "r"(a[1]), "r"(a[2]), "r"(a[3]),
          "r"(b[0]), "r"(b[1]));
}
__device__ __forceinline__ void cpa16(uint32_t dst, const void* src) {
    asm volatile("cp.async.cg.shared.global [%0], [%1], 16;"
                 :: "r"(dst), "l"(src));
}
#define CP_COMMIT() asm volatile("cp.async.commit_group;" ::: "memory")
#define CP_WAIT3()  asm volatile("cp.async.wait_group 3;" ::: "memory")

// ==================================================================
// conv_a: fp32 [512,4096] -> bf16 hi/lo swizzled 16KB tiles
// ==================================================================
__global__ __launch_bounds__(256) void conv_a(const float* __restrict__ A,
                                              char* __restrict__ out)
{
    int idx = blockIdx.x * 256 + threadIdx.x;   // 512 rows * 512 k8 groups
    int row = idx >> 9, k8 = idx & 511;
    float4 v0 = *(const float4*)(A + (size_t)row * HID_ + k8 * 8);
    float4 v1 = *(const float4*)(A + (size_t)row * HID_ + k8 * 8 + 4);
    uint32_t h[4], l[4];
    split4(v0, h, l);
    split4(v1, h + 2, l + 2);
    int row_local = row & 127, mblk = row >> 7;
    int c = k8 >> 2, c16 = k8 & 3;
    int off = row_local * 64 + ((c16 ^ ((row_local >> 1) & 3)) << 4);
    char* base = out + (size_t)(mblk * 128 + c) * 16384;
    *(uint4*)(base + off)        = make_uint4(h[0], h[1], h[2], h[3]);
    *(uint4*)(base + 8192 + off) = make_uint4(l[0], l[1], l[2], l[3]);
}

// ==================================================================
// Hybrid GEMM, 512 threads / 16 warps, 32x32 warp tiles.
// A via 4-stage cp.async from pre-converted tiles; B register-convert
// spread over 512 threads (8 fp32 each).
// ==================================================================
#define BKC 32
#define NCH (HID_ / BKC)      // 128
#define ATILE 16384
#define BTILE 16384
#define GSMEM  (4 * ATILE + 2 * BTILE + 128)

__global__ __launch_bounds__(512, 1)
void gemm_hyb(const char* __restrict__ Xt,
              const float* __restrict__ B0, const float* __restrict__ B1,
              const float* __restrict__ B2,
              float* __restrict__ C, int Nper, int Ntot)
{
    extern __shared__ char dynsm[];
    uint32_t sraw = smem_u32(dynsm);
    uint32_t smb = (sraw + 127u) & ~127u;
    uint32_t aBase = smb;
    uint32_t bBase = smb + 4 * ATILE;
    char* smp = dynsm + (smb - sraw);

    int tid = threadIdx.x, lane = tid & 31, wid = tid >> 5;
    int mblk = blockIdx.y;
    int m0 = mblk * 128, col0 = blockIdx.x * 128;

    const float* Bp; int nloc;
    if (col0 < Nper)          { Bp = B0; nloc = col0; }
    else if (col0 < 2 * Nper) { Bp = B1; nloc = col0 - Nper; }
    else                      { Bp = B2; nloc = col0 - 2 * Nper; }
    size_t NperS = (size_t)Nper;

    // B convert role: thread (nB, kg): 8 k-values (one 16B chunk)
    int nB = tid & 127, kg = tid >> 7;        // kg in 0..3
    const float* Bptr = Bp + nloc + nB;
    int rxB = (nB >> 1) & 3;
    int sB_off = nB * 64 + ((kg ^ rxB) << 4);

    // A copy role: 512 threads x 32B per 16KB stage
    const char* aSrc = Xt + (size_t)mblk * 128 * ATILE + tid * 32;
    uint32_t aDstOff = (uint32_t)(tid * 32);

    // consumer mapping: 32x32 warp tile
    int wm = wid & 3, wn = wid >> 2;
    int aRow = wm * 32 + ((lane >> 3) & 1) * 8 + (lane & 7);
    int aCh  = (lane >> 4) & 1;
    int aRX  = (aRow >> 1) & 3;
    uint32_t aOff = (uint32_t)(aRow * 64);
    int nbRow = wn * 32 + ((lane >> 4) & 1) * 8 + (lane & 7);
    int bCh  = (lane >> 3) & 1;
    int bRX  = (nbRow >> 1) & 3;
    uint32_t nbOff = (uint32_t)(nbRow * 64);

    float acc[2][4][4];
#pragma unroll
    for (int i = 0; i < 2; i++)
#pragma unroll
        for (int j = 0; j < 4; j++)
#pragma unroll
            for (int e = 0; e < 4; e++) acc[i][j][e] = 0.f;

    // prologue: A stages 0..2 in flight, B(0) in regs
#pragma unroll
    for (int s = 0; s < 3; s++) {
        uint32_t dst = aBase + s * ATILE + aDstOff;
        const char* src = aSrc + (size_t)s * ATILE;
        cpa16(dst, src);
        cpa16(dst + 16, src + 16);
        CP_COMMIT();
    }
    float pb[8];
    {
        const float* bp = Bptr + (size_t)(kg * 8) * NperS;
#pragma unroll
        for (int j = 0; j < 8; j++) pb[j] = bp[(size_t)j * NperS];
    }

    for (int c = 0; c < NCH; c++) {
        // STS B(c)
        {
            char* bb = smp + 4 * ATILE + (c & 1) * BTILE;
            uint32_t h[4], l[4];
            split4(make_float4(pb[0], pb[1], pb[2], pb[3]), h, l);
            split4(make_float4(pb[4], pb[5], pb[6], pb[7]), h + 2, l + 2);
            *(uint4*)(bb + sB_off)        = make_uint4(h[0], h[1], h[2], h[3]);
            *(uint4*)(bb + 8192 + sB_off) = make_uint4(l[0], l[1], l[2], l[3]);
        }
        // issue A(c+3)
        if (c + 3 < NCH) {
            uint32_t dst = aBase + ((c + 3) & 3) * ATILE + aDstOff;
            const char* src = aSrc + (size_t)(c + 3) * ATILE;
            cpa16(dst, src);
            cpa16(dst + 16, src + 16);
        }
        CP_COMMIT();
        CP_WAIT3();          // A(c) complete
        __syncthreads();     // B(c) + A(c) visible

        // prefetch B(c+1)
        if (c + 1 < NCH) {
            const float* bp = Bptr + (size_t)((c + 1) * BKC + kg * 8) * NperS;
#pragma unroll
            for (int j = 0; j < 8; j++) pb[j] = bp[(size_t)j * NperS];
        }

        uint32_t stageA = aBase + (c & 3) * ATILE;
        uint32_t stageB = bBase + (c & 1) * BTILE;
#pragma unroll
        for (int s = 0; s < 2; s++) {
            uint32_t bfh[4][2], bfl[4][2];
#pragma unroll
            for (int half = 0; half < 2; half++) {
                uint32_t addr = stageB + half * 1024 + nbOff
                              + ((((s * 2) + bCh) ^ bRX) << 4);
                uint32_t r[4];
                ldsm4(r, addr);
                bfh[half * 2][0] = r[0]; bfh[half * 2][1] = r[1];
                bfh[half * 2 + 1][0] = r[2]; bfh[half * 2 + 1][1] = r[3];
                ldsm4(r, addr + 8192);
                bfl[half * 2][0] = r[0]; bfl[half * 2][1] = r[1];
                bfl[half * 2 + 1][0] = r[2]; bfl[half * 2 + 1][1] = r[3];
            }
#pragma unroll
            for (int mt = 0; mt < 2; mt++) {
                uint32_t addr = stageA + mt * 1024 + aOff
                              + ((((s * 2) + aCh) ^ aRX) << 4);
                uint32_t ah[4], al[4];
                ldsm4(ah, addr);
                ldsm4(al, addr + 8192);
#pragma unroll
                for (int nt = 0; nt < 4; nt++) mma16816(acc[mt][nt], ah, bfh[nt]);
#pragma unroll
                for (int nt = 0; nt < 4; nt++) mma16816(acc[mt][nt], ah, bfl[nt]);
#pragma unroll
                for (int nt = 0; nt < 4; nt++) mma16816(acc[mt][nt], al, bfh[nt]);
            }
        }
        __syncthreads();
    }

#pragma unroll
    for (int mt = 0; mt < 2; mt++) {
        int row = m0 + wm * 32 + mt * 16 + (lane >> 2);
#pragma unroll
        for (int nt = 0; nt < 4; nt++) {
            int col = col0 + wn * 32 + nt * 8 + (lane & 3) * 2;
            *(float2*)(C + (size_t)row * Ntot + col) =
                make_float2(acc[mt][nt][0], acc[mt][nt][1]);
            *(float2*)(C + (size_t)(row + 8) * Ntot + col) =
                make_float2(acc[mt][nt][2], acc[mt][nt][3]);
        }
    }
}

// ------------------------------------------------------------------
// RoPE in place on q/k of g_qkv.
// ------------------------------------------------------------------
__global__ __launch_bounds__(256) void rope_k(const int* __restrict__ pos_ids)
{
    int idx = blockIdx.x * 256 + threadIdx.x;
    int i = idx & 63;
    int h = (idx >> 6) & 63;
    int t = idx >> 12;
    if (t >= T_) return;

    float p = (float)pos_ids[t];
    float inv = expf((float)i * (-9.210340371976184f / 64.0f));
    float ang = p * inv;
    float s, c;
    sincosf(ang, &s, &c);

    size_t base = (size_t)t * QKVW + (size_t)h * D_ + i;
    float x0 = g_qkv[base];
    float x1 = g_qkv[base + 64];
    g_qkv[base]      = x0 * c - x1 * s;
    g_qkv[base + 64] = x1 * c + x0 * s;
}

// ==================================================================
// Tensor-core flash attention, 512 threads / 16 warps.
// QK warp tile 16q x 16k; PV warp tile 16q x 32d.
// 3-phase pipeline: A: QK||V-load ; B: softmax ; C: PV||K(t+1)-load
// ==================================================================
#define AQH 0u
#define AQL 16384u
#define AKH 32768u
#define AKL 49152u
#define AVH 65536u
#define AVL 81920u
#define ASS 98304u
#define APH 115712u
#define APL 123904u
#define AST 132096u
#define ATTN_SMEM 133120

__device__ __forceinline__ void kv_src(int t, int b, int n,
                                       const float* cache,
                                       const int* __restrict__ block_offsets,
                                       int qkv_off,
                                       const float*& ptr, size_t& str)
{
    if (t < 32) {
        int blk = block_offsets[b * NBLK_ + t];
        ptr = cache + ((size_t)blk * BSZ_ * NKV_ + n) * D_;
        str = (size_t)NKV_ * D_;
    } else {
        ptr = g_qkv + (size_t)b * S_ * QKVW + qkv_off + (size_t)n * D_;
        str = QKVW;
    }
}

__global__ __launch_bounds__(512, 1) void attn_tc(
    const float* __restrict__ k_cache, const float* __restrict__ v_cache,
    const int* __restrict__ pos_ids, const int* __restrict__ block_offsets)
{
    extern __shared__ char smc[];
    uint32_t smb = smem_u32(smc);
    float* s_s   = (float*)(smc + ASS);
    float* row_m = (float*)(smc + AST);
    float* row_l = row_m + 64;
    float* row_c = row_l + 64;
    int*   pos_s = (int*)(row_c + 64);

    int n = blockIdx.x, b = blockIdx.y;
    int tid = threadIdx.x, lane = tid & 31, wid = tid >> 5;
    int wm = wid & 3, wn = wid >> 2;   // wm: 16-row group, wn: 16-key/32-dim group

    int ldrow = tid >> 5, ldq = tid & 31;   // ldrow 0..15
    int ldoff = ldrow * 256 + (((ldq >> 1) ^ (ldrow & 7)) << 4) + (ldq & 1) * 8;

    const float* qbase = g_qkv + (size_t)b * S_ * QKVW + (size_t)n * D_;
    {
        const float* kb; size_t kstr;
        kv_src(0, b, n, k_cache, block_offsets, HID_, kb, kstr);
#pragma unroll
        for (int i = 0; i < 4; i++) {
            int row = ldrow + i * 16;
            int off = ldoff + i * 16 * 256;
            float4 v = *(const float4*)(qbase + (size_t)row * QKVW + ldq * 4);
            uint32_t h[2], l[2];
            split4(v, h, l);
            *(uint2*)(smc + AQH + off) = make_uint2(h[0], h[1]);
            *(uint2*)(smc + AQL + off) = make_uint2(l[0], l[1]);
            float4 w = *(const float4*)(kb + (size_t)row * kstr + ldq * 4);
            split4(w, h, l);
            *(uint2*)(smc + AKH + off) = make_uint2(h[0], h[1]);
            *(uint2*)(smc + AKL + off) = make_uint2(l[0], l[1]);
        }
    }
    if (tid < 64) {
        row_m[tid] = -3.0e38f;
        row_l[tid] = 0.f;
        pos_s[tid] = pos_ids[b * S_ + tid];
    }
    __syncthreads();

    float accO[4][4];
#pragma unroll
    for (int i = 0; i < 4; i++)
#pragma unroll
        for (int e = 0; e < 4; e++) accO[i][e] = 0.f;

    const float scale = 0.08838834764831845f;

    int arow  = wm * 16 + ((lane >> 3) & 1) * 8 + (lane & 7);
    int nbRow = wn * 16 + ((lane >> 4) & 1) * 8 + (lane & 7);
    int prow  = arow;
    int vkeyb = ((lane >> 3) & 1) * 8 + (lane & 7);
    int achq  = (lane >> 4) & 1;
    int bchq  = (lane >> 3) & 1;

    for (int t = 0; t < 33; t++) {
        // ===== phase A: V-load(t) || QK MMA =====
        const float* vb; size_t vstr;
        kv_src(t, b, n, v_cache, block_offsets, 2 * HID_, vb, vstr);
        float4 vv[4];
#pragma unroll
        for (int i = 0; i < 4; i++)
            vv[i] = *(const float4*)(vb + (size_t)(ldrow + i * 16) * vstr + ldq * 4);

        float accs[2][4];
#pragma unroll
        for (int i = 0; i < 2; i++)
#pragma unroll
            for (int e = 0; e < 4; e++) accs[i][e] = 0.f;

#pragma unroll
        for (int ks = 0; ks < 8; ks++) {
            uint32_t ah[4], al[4];
            uint32_t aaddr = smb + AQH + arow * 256
                           + (((2 * ks + achq) ^ (arow & 7)) << 4);
            ldsm4(ah, aaddr);
            ldsm4(al, aaddr + (AQL - AQH));
            uint32_t bh[2][2], bl[2][2];
            {
                uint32_t baddr = smb + AKH + nbRow * 256
                               + (((2 * ks + bchq) ^ (nbRow & 7)) << 4);
                uint32_t r[4];
                ldsm4(r, baddr);
                bh[0][0] = r[0]; bh[0][1] = r[1];
                bh[1][0] = r[2]; bh[1][1] = r[3];
                ldsm4(r, baddr + (AKL - AKH));
                bl[0][0] = r[0]; bl[0][1] = r[1];
                bl[1][0] = r[2]; bl[1][1] = r[3];
            }
#pragma unroll
            for (int nt = 0; nt < 2; nt++) mma16816(accs[nt], ah, bh[nt]);
#pragma unroll
            for (int nt = 0; nt < 2; nt++) mma16816(accs[nt], ah, bl[nt]);
#pragma unroll
            for (int nt = 0; nt < 2; nt++) mma16816(accs[nt], al, bh[nt]);
        }
        // V convert + STS
#pragma unroll
        for (int i = 0; i < 4; i++) {
            int off = ldoff + i * 16 * 256;
            uint32_t h[2], l[2];
            split4(vv[i], h, l);
            *(uint2*)(smc + AVH + off) = make_uint2(h[0], h[1]);
            *(uint2*)(smc + AVL + off) = make_uint2(l[0], l[1]);
        }
        // S store
        {
            int r0 = wm * 16 + (lane >> 2);
            int c0 = wn * 16 + (lane & 3) * 2;
#pragma unroll
            for (int nt = 0; nt < 2; nt++) {
                *(float2*)&s_s[r0 * 68 + c0 + nt * 8] =
                    make_float2(accs[nt][0] * scale, accs[nt][1] * scale);
                *(float2*)&s_s[(r0 + 8) * 68 + c0 + nt * 8] =
                    make_float2(accs[nt][2] * scale, accs[nt][3] * scale);
            }
        }
        __syncthreads();

        // ===== phase B: online softmax (8 threads/row) =====
        {
            int r = tid >> 3, u = tid & 7;
            int lb = t * 64, pr = pos_s[r];
            bool nm = (lb + 63 > pr);
            float p8[8];
            float mloc = -3.0e38f;
#pragma unroll
            for (int jj = 0; jj < 8; jj++) {
                int j = u * 8 + jj;
                float sv = s_s[r * 68 + j];
                p8[jj] = sv;
                if (!nm || lb + j <= pr) mloc = fmaxf(mloc, sv);
            }
            mloc = fmaxf(mloc, __shfl_xor_sync(0xffffffffu, mloc, 1));
            mloc = fmaxf(mloc, __shfl_xor_sync(0xffffffffu, mloc, 2));
            mloc = fmaxf(mloc, __shfl_xor_sync(0xffffffffu, mloc, 4));
            float mnew = fmaxf(row_m[r], mloc);
            float sum = 0.f;
#pragma unroll
            for (int jj = 0; jj < 8; jj++) {
                int j = u * 8 + jj;
                float pv = 0.f;
                if (!nm || lb + j <= pr) pv = expf(p8[jj] - mnew);
                p8[jj] = pv;
                sum += pv;
            }
            sum += __shfl_xor_sync(0xffffffffu, sum, 1);
            sum += __shfl_xor_sync(0xffffffffu, sum, 2);
            sum += __shfl_xor_sync(0xffffffffu, sum, 4);
            // pack 8 p-values -> one uint4 hi + one uint4 lo
            {
                uint32_t hw[4], lw[4];
#pragma unroll
                for (int qd = 0; qd < 4; qd++) {
                    float x0 = p8[qd * 2], x1 = p8[qd * 2 + 1];
                    hw[qd] = pack_bf2(x0, x1);
                    float2 f = unpack_bf2(hw[qd]);
                    lw[qd] = pack_bf2(x0 - f.x, x1 - f.y);
                }
                int off = r * 128 + ((u ^ (r & 7)) << 4);
                *(uint4*)(smc + APH + off) = make_uint4(hw[0], hw[1], hw[2], hw[3]);
                *(uint4*)(smc + APL + off) = make_uint4(lw[0], lw[1], lw[2], lw[3]);
            }
            if (u == 0) {
                float corr = expf(row_m[r] - mnew);
                row_c[r] = corr;
                row_l[r] = row_l[r] * corr + sum;
                row_m[r] = mnew;
            }
        }
        __syncthreads();

        // ===== phase C: K(t+1)-load || PV MMA =====
        {
            int tn = t + 1 < 33 ? t + 1 : 32;
            const float* kb; size_t kstr;
            kv_src(tn, b, n, k_cache, block_offsets, HID_, kb, kstr);
            float4 kk[4];
#pragma unroll
            for (int i = 0; i < 4; i++)
                kk[i] = *(const float4*)(kb + (size_t)(ldrow + i * 16) * kstr + ldq * 4);

            float c0f = row_c[wm * 16 + (lane >> 2)];
            float c1f = row_c[wm * 16 + (lane >> 2) + 8];
#pragma unroll
            for (int nt = 0; nt < 4; nt++) {
                accO[nt][0] *= c0f; accO[nt][1] *= c0f;
                accO[nt][2] *= c1f; accO[nt][3] *= c1f;
            }
            uint32_t ph[4], pl[4];
#pragma unroll
            for (int idx = 0; idx < 8; idx++) {
                int ks = idx >> 1, pr2 = idx & 1;
                if (pr2 == 0) {
                    uint32_t paddr = smb + APH + prow * 128
                                   + (((2 * ks + achq) ^ (prow & 7)) << 4);
                    ldsm4(ph, paddr);
                    ldsm4(pl, paddr + (APL - APH));
                }
                int key = ks * 16 + vkeyb;
                int dch = wn * 4 + pr2 * 2 + achq;
                uint32_t vaddr = smb + AVH + key * 256
                               + ((dch ^ (key & 7)) << 4);
                uint32_t rh[4], rl[4];
                ldsm4t(rh, vaddr);
                ldsm4t(rl, vaddr + (AVL - AVH));
                uint32_t bh0[2] = { rh[0], rh[1] }, bh1[2] = { rh[2], rh[3] };
                uint32_t bl0[2] = { rl[0], rl[1] }, bl1[2] = { rl[2], rl[3] };
                mma16816(accO[pr2 * 2],     ph, bh0);
                mma16816(accO[pr2 * 2 + 1], ph, bh1);
                mma16816(accO[pr2 * 2],     ph, bl0);
                mma16816(accO[pr2 * 2 + 1], ph, bl1);
                mma16816(accO[pr2 * 2],     pl, bh0);
                mma16816(accO[pr2 * 2 + 1], pl, bh1);
            }
            // K convert + STS
#pragma unroll
            for (int i = 0; i < 4; i++) {
                int off = ldoff + i * 16 * 256;
                uint32_t h[2], l[2];
                split4(kk[i], h, l);
                *(uint2*)(smc + AKH + off) = make_uint2(h[0], h[1]);
                *(uint2*)(smc + AKL + off) = make_uint2(l[0], l[1]);
            }
        }
        __syncthreads();
    }

    // ---- epilogue ----
    int r0 = wm * 16 + (lane >> 2);
    float il0 = 1.0f / row_l[r0];
    float il1 = 1.0f / row_l[r0 + 8];
    float* ob0 = g_attn + (size_t)(b * S_ + r0) * HID_ + (size_t)n * D_
               + wn * 32 + (lane & 3) * 2;
    float* ob1 = ob0 + 8 * HID_;
#pragma unroll
    for (int nt = 0; nt < 4; nt++) {
        *(float2*)(ob0 + nt * 8) = make_float2(accO[nt][0] * il0, accO[nt][1] * il0);
        *(float2*)(ob1 + nt * 8) = make_float2(accO[nt][2] * il1, accO[nt][3] * il1);
    }
}

// ------------------------------------------------------------------
// Launch
// ------------------------------------------------------------------
extern "C" void kernel_launch(void* const* d_in, const int* in_sizes, int n_in,
                              void* d_out, int out_size)
{
    const float* X  = (const float*)d_in[0];
    const float* kc = (const float*)d_in[1];
    const float* vc = (const float*)d_in[2];
    const float* wq = (const float*)d_in[3];
    const float* wk = (const float*)d_in[4];
    const float* wv = (const float*)d_in[5];
    const float* wo = (const float*)d_in[6];
    const int* pos  = (const int*)d_in[7];
    const int* bo   = (const int*)d_in[8];
    float* out = (float*)d_out;

    float *qkv_p, *attn_p;
    char *xt_p;
    cudaGetSymbolAddress((void**)&qkv_p, g_qkv);
    cudaGetSymbolAddress((void**)&attn_p, g_attn);
    cudaGetSymbolAddress((void**)&xt_p, g_xt);

    cudaFuncSetAttribute(gemm_hyb, cudaFuncAttributeMaxDynamicSharedMemorySize,
                         GSMEM);
    cudaFuncSetAttribute(attn_tc, cudaFuncAttributeMaxDynamicSharedMemorySize,
                         ATTN_SMEM);

    // 0) convert X to bf16 hi/lo tiles
    conv_a<<<1024, 256>>>(X, xt_p);

    // 1) fused QKV projection
    gemm_hyb<<<dim3(96, 4), 512, GSMEM>>>(xt_p, wq, wk, wv, qkv_p, HID_, QKVW);

    // 2) RoPE on q and k
    rope_k<<<(T_ * 64 * 64) / 256, 256>>>(pos);

    // 3) paged causal flash attention
    attn_tc<<<dim3(NH_, B_), 512, ATTN_SMEM>>>(kc, vc, pos, bo);

    // 4) convert attention output + output projection
    conv_a<<<1024, 256>>>(attn_p, xt_p);
    gemm_hyb<<<dim3(32, 4), 512, GSMEM>>>(xt_p, wo, wo, wo, out, HID_, HID_);
}

// round 15
// speedup vs baseline: 1.0372x; 1.0372x over previous
#include <cuda_runtime.h>
#include <cuda_bf16.h>
#include <math.h>
#include <stdint.h>

// Problem constants
#define B_    8
#define S_    64
#define T_    512
#define HID_  4096
#define NH_   32
#define NKV_  32
#define D_    128
#define HIST_ 2048
#define BSZ_  64
#define NBLK_ 33
#define L_    2112
#define QKVW  12288   // 3 * HID_

__device__ float g_qkv[(size_t)T_ * QKVW];
__device__ float g_attn[(size_t)T_ * HID_];
// Pre-converted activation tiles: 4 mblk x 128 chunks x 16KB (hi 8K | lo 8K)
__device__ __align__(16) char g_xt[(size_t)8388608];

// ==================================================================
// Helpers
// ==================================================================
__device__ __forceinline__ uint32_t smem_u32(const void* p) {
    return (uint32_t)__cvta_generic_to_shared(p);
}
__device__ __forceinline__ uint32_t pack_bf2(float x0, float x1) {
    uint32_t d;
    asm("cvt.rn.bf16x2.f32 %0, %1, %2;" : "=r"(d) : "f"(x1), "f"(x0));
    return d;
}
__device__ __forceinline__ float2 unpack_bf2(uint32_t u) {
    float2 r;
    r.x = __uint_as_float(u << 16);
    r.y = __uint_as_float(u & 0xffff0000u);
    return r;
}
__device__ __forceinline__ void split4(float4 v, uint32_t* hi, uint32_t* lo) {
    uint32_t h0 = pack_bf2(v.x, v.y);
    uint32_t h1 = pack_bf2(v.z, v.w);
    float2 f0 = unpack_bf2(h0), f1 = unpack_bf2(h1);
    hi[0] = h0; hi[1] = h1;
    lo[0] = pack_bf2(v.x - f0.x, v.y - f0.y);
    lo[1] = pack_bf2(v.z - f1.x, v.w - f1.y);
}
__device__ __forceinline__ void ldsm4(uint32_t* r, uint32_t addr) {
    asm volatile("ldmatrix.sync.aligned.m8n8.x4.shared.b16 {%0,%1,%2,%3}, [%4];"
                 : "=r"(r[0]), "=r"(r[1]), "=r"(r[2]), "=r"(r[3]) : "r"(addr));
}
__device__ __forceinline__ void ldsm4t(uint32_t* r, uint32_t addr) {
    asm volatile("ldmatrix.sync.aligned.m8n8.x4.trans.shared.b16 {%0,%1,%2,%3}, [%4];"
                 : "=r"(r[0]), "=r"(r[1]), "=r"(r[2]), "=r"(r[3]) : "r"(addr));
}
__device__ __forceinline__ void mma16816(float* d, const uint32_t* a, const uint32_t* b) {
    asm("mma.sync.aligned.m16n8k16.row.col.f32.bf16.bf16.f32 "
        "{%0,%1,%2,%3}, {%4,%5,%6,%7}, {%8,%9}, {%0,%1,%2,%3};"
        : "+f"(d[0]), "+f"(d[1]), "+f"(d[2]), "+f"(d[3])
        : "r"(a[0]), "r"(a[1]), "r"(a[2]), "r"(a[3]),
          "r"(b[0]), "r"(b[1]));
}
__device__ __forceinline__ void cpa16(uint32_t dst, const void* src) {
    asm volatile("cp.async.cg.shared.global [%0], [%1], 16;"
                 :: "r"(dst), "l"(src));
}
#define CP_COMMIT() asm volatile("cp.async.commit_group;" ::: "memory")
#define CP_WAIT1()  asm volatile("cp.async.wait_group 1;" ::: "memory")

// ==================================================================
// conv_a: fp32 [512,4096] -> bf16 hi/lo swizzled 16KB tiles
// ==================================================================
__global__ __launch_bounds__(256) void conv_a(const float* __restrict__ A,
                                              char* __restrict__ out)
{
    int idx = blockIdx.x * 256 + threadIdx.x;   // 512 rows * 512 k8 groups
    int row = idx >> 9, k8 = idx & 511;
    float4 v0 = *(const float4*)(A + (size_t)row * HID_ + k8 * 8);
    float4 v1 = *(const float4*)(A + (size_t)row * HID_ + k8 * 8 + 4);
    uint32_t h[4], l[4];
    split4(v0, h, l);
    split4(v1, h + 2, l + 2);
    int row_local = row & 127, mblk = row >> 7;
    int c = k8 >> 2, c16 = k8 & 3;
    int off = row_local * 64 + ((c16 ^ ((row_local >> 1) & 3)) << 4);
    char* base = out + (size_t)(mblk * 128 + c) * 16384;
    *(uint4*)(base + off)        = make_uint4(h[0], h[1], h[2], h[3]);
    *(uint4*)(base + 8192 + off) = make_uint4(l[0], l[1], l[2], l[3]);
}

// ==================================================================
// Warp-specialized GEMM (R12, best measured): 384 threads.
//  warps 0-7  (consumers): ldmatrix + MMA, 64x32 warp tiles
//  warps 8-11 (producers): B LDG -> bf16 hi/lo -> STS; A cp.async
// ==================================================================
#define BKC 32
#define NCH (HID_ / BKC)      // 128
#define ATILE 16384
#define BTILE 16384
#define GSMEM  (4 * ATILE + 2 * BTILE + 128)

__global__ __launch_bounds__(384, 1)
void gemm_ws(const char* __restrict__ Xt,
             const float* __restrict__ B0, const float* __restrict__ B1,
             const float* __restrict__ B2,
             float* __restrict__ C, int Nper, int Ntot)
{
    extern __shared__ char dynsm[];
    uint32_t sraw = smem_u32(dynsm);
    uint32_t smb = (sraw + 127u) & ~127u;
    uint32_t aBase = smb;
    uint32_t bBase = smb + 4 * ATILE;
    char* smp = dynsm + (smb - sraw);

    int tid = threadIdx.x, lane = tid & 31, wid = tid >> 5;
    int mblk = blockIdx.y;
    int m0 = mblk * 128, col0 = blockIdx.x * 128;
    bool producer = (wid >= 8);

    const float* Bp; int nloc;
    if (col0 < Nper)          { Bp = B0; nloc = col0; }
    else if (col0 < 2 * Nper) { Bp = B1; nloc = col0 - Nper; }
    else                      { Bp = B2; nloc = col0 - 2 * Nper; }
    size_t NperS = (size_t)Nper;

    // ---------------- producer state ----------------
    int pt = tid - 256;
    const float* Bptr = Bp + nloc + (pt & 127);
    int rxB = ((pt & 127) >> 1) & 3;
    const char* aSrcBase = Xt + (size_t)mblk * 128 * ATILE + (pt & 127) * 128;
    uint32_t aDstOff = (uint32_t)((pt & 127) * 128);
    float pb[32];

    // ---------------- consumer state ----------------
    int wm = wid & 1, wn = wid >> 1;
    int aRow = wm * 64 + ((lane >> 3) & 1) * 8 + (lane & 7);
    int aCh  = (lane >> 4) & 1;
    int aRX  = (aRow >> 1) & 3;
    uint32_t aOff = (uint32_t)(aRow * 64);
    int nbRow = wn * 32 + ((lane >> 4) & 1) * 8 + (lane & 7);
    int bCh  = (lane >> 3) & 1;
    int bRX  = (nbRow >> 1) & 3;
    uint32_t nbOff = (uint32_t)(nbRow * 64);

    float acc[4][4][4];
#pragma unroll
    for (int i = 0; i < 4; i++)
#pragma unroll
        for (int j = 0; j < 4; j++)
#pragma unroll
            for (int e = 0; e < 4; e++) acc[i][j][e] = 0.f;

    // ---------------- prologue (producers) ----------------
    if (producer) {
#pragma unroll
        for (int j = 0; j < 32; j++) pb[j] = Bptr[(size_t)j * NperS];
        {
            char* bb = smp + 4 * ATILE;
#pragma unroll
            for (int c16 = 0; c16 < 4; c16++) {
                uint32_t h[2], l[2], h2[2], l2[2];
                split4(make_float4(pb[c16*8+0], pb[c16*8+1], pb[c16*8+2], pb[c16*8+3]), h, l);
                split4(make_float4(pb[c16*8+4], pb[c16*8+5], pb[c16*8+6], pb[c16*8+7]), h2, l2);
                int off = (pt & 127) * 64 + ((c16 ^ rxB) << 4);
                *(uint4*)(bb + off)        = make_uint4(h[0], h[1], h2[0], h2[1]);
                *(uint4*)(bb + 8192 + off) = make_uint4(l[0], l[1], l2[0], l2[1]);
            }
        }
#pragma unroll
        for (int j = 0; j < 32; j++) pb[j] = Bptr[(size_t)(BKC + j) * NperS];
#pragma unroll
        for (int s = 0; s < 2; s++) {
            uint32_t dst = aBase + s * ATILE + aDstOff;
            const char* src = aSrcBase + (size_t)s * ATILE;
#pragma unroll
            for (int q = 0; q < 8; q++) cpa16(dst + q * 16, src + q * 16);
            CP_COMMIT();
        }
        CP_WAIT1();
    }
    __syncthreads();

    // ---------------- main loop ----------------
    for (int c = 0; c < NCH; c++) {
        if (producer) {
            if (c + 1 < NCH) {
                char* bb = smp + 4 * ATILE + ((c + 1) & 1) * BTILE;
#pragma unroll
                for (int c16 = 0; c16 < 4; c16++) {
                    uint32_t h[2], l[2], h2[2], l2[2];
                    split4(make_float4(pb[c16*8+0], pb[c16*8+1], pb[c16*8+2], pb[c16*8+3]), h, l);
                    split4(make_float4(pb[c16*8+4], pb[c16*8+5], pb[c16*8+6], pb[c16*8+7]), h2, l2);
                    int off = (pt & 127) * 64 + ((c16 ^ rxB) << 4);
                    *(uint4*)(bb + off)        = make_uint4(h[0], h[1], h2[0], h2[1]);
                    *(uint4*)(bb + 8192 + off) = make_uint4(l[0], l[1], l2[0], l2[1]);
                }
            }
            if (c + 2 < NCH) {
                const float* bp = Bptr + (size_t)((c + 2) * BKC) * NperS;
#pragma unroll
                for (int j = 0; j < 32; j++) pb[j] = bp[(size_t)j * NperS];
                uint32_t dst = aBase + ((c + 2) & 3) * ATILE + aDstOff;
                const char* src = aSrcBase + (size_t)(c + 2) * ATILE;
#pragma unroll
                for (int q = 0; q < 8; q++) cpa16(dst + q * 16, src + q * 16);
            }
            CP_COMMIT();
            CP_WAIT1();
        } else {
            uint32_t stageA = aBase + (c & 3) * ATILE;
            uint32_t stageB = bBase + (c & 1) * BTILE;
#pragma unroll
            for (int s = 0; s < 2; s++) {
                uint32_t bfh[4][2], bfl[4][2];
#pragma unroll
                for (int half = 0; half < 2; half++) {
                    uint32_t addr = stageB + half * 1024 + nbOff
                                  + ((((s * 2) + bCh) ^ bRX) << 4);
                    uint32_t r[4];
                    ldsm4(r, addr);
                    bfh[half * 2][0] = r[0]; bfh[half * 2][1] = r[1];
                    bfh[half * 2 + 1][0] = r[2]; bfh[half * 2 + 1][1] = r[3];
                    ldsm4(r, addr + 8192);
                    bfl[half * 2][0] = r[0]; bfl[half * 2][1] = r[1];
                    bfl[half * 2 + 1][0] = r[2]; bfl[half * 2 + 1][1] = r[3];
                }
                uint32_t ahb[2][4], alb[2][4];
                {
                    uint32_t addr = stageA + aOff
                                  + ((((s * 2) + aCh) ^ aRX) << 4);
                    ldsm4(ahb[0], addr);
                    ldsm4(alb[0], addr + 8192);
                }
#pragma unroll
                for (int mt = 0; mt < 4; mt++) {
                    int cur = mt & 1;
                    if (mt < 3) {
                        uint32_t addr = stageA + (mt + 1) * 1024 + aOff
                                      + ((((s * 2) + aCh) ^ aRX) << 4);
                        ldsm4(ahb[cur ^ 1], addr);
                        ldsm4(alb[cur ^ 1], addr + 8192);
                    }
#pragma unroll
                    for (int nt = 0; nt < 4; nt++) mma16816(acc[mt][nt], ahb[cur], bfh[nt]);
#pragma unroll
                    for (int nt = 0; nt < 4; nt++) mma16816(acc[mt][nt], ahb[cur], bfl[nt]);
#pragma unroll
                    for (int nt = 0; nt < 4; nt++) mma16816(acc[mt][nt], alb[cur], bfh[nt]);
                }
            }
        }
        __syncthreads();
    }

    // ---------------- epilogue (consumers) ----------------
    if (!producer) {
#pragma unroll
        for (int mt = 0; mt < 4; mt++) {
            int row = m0 + wm * 64 + mt * 16 + (lane >> 2);
#pragma unroll
            for (int nt = 0; nt < 4; nt++) {
                int col = col0 + wn * 32 + nt * 8 + (lane & 3) * 2;
                *(float2*)(C + (size_t)row * Ntot + col) =
                    make_float2(acc[mt][nt][0], acc[mt][nt][1]);
                *(float2*)(C + (size_t)(row + 8) * Ntot + col) =
                    make_float2(acc[mt][nt][2], acc[mt][nt][3]);
            }
        }
    }
}

// ------------------------------------------------------------------
// RoPE in place on q/k of g_qkv.
// ------------------------------------------------------------------
__global__ __launch_bounds__(256) void rope_k(const int* __restrict__ pos_ids)
{
    int idx = blockIdx.x * 256 + threadIdx.x;
    int i = idx & 63;
    int h = (idx >> 6) & 63;
    int t = idx >> 12;
    if (t >= T_) return;

    float p = (float)pos_ids[t];
    float inv = expf((float)i * (-9.210340371976184f / 64.0f));
    float ang = p * inv;
    float s, c;
    sincosf(ang, &s, &c);

    size_t base = (size_t)t * QKVW + (size_t)h * D_ + i;
    float x0 = g_qkv[base];
    float x1 = g_qkv[base + 64];
    g_qkv[base]      = x0 * c - x1 * s;
    g_qkv[base + 64] = x1 * c + x0 * s;
}

// ==================================================================
// Tensor-core flash attention (R13, best measured): 512 threads,
// 16 warps, QK tile 16x16, PV tile 16x32, 3-phase pipeline.
// ==================================================================
#define AQH 0u
#define AQL 16384u
#define AKH 32768u
#define AKL 49152u
#define AVH 65536u
#define AVL 81920u
#define ASS 98304u
#define APH 115712u
#define APL 123904u
#define AST 132096u
#define ATTN_SMEM 133120

__device__ __forceinline__ void kv_src(int t, int b, int n,
                                       const float* cache,
                                       const int* __restrict__ block_offsets,
                                       int qkv_off,
                                       const float*& ptr, size_t& str)
{
    if (t < 32) {
        int blk = block_offsets[b * NBLK_ + t];
        ptr = cache + ((size_t)blk * BSZ_ * NKV_ + n) * D_;
        str = (size_t)NKV_ * D_;
    } else {
        ptr = g_qkv + (size_t)b * S_ * QKVW + qkv_off + (size_t)n * D_;
        str = QKVW;
    }
}

__global__ __launch_bounds__(512, 1) void attn_tc(
    const float* __restrict__ k_cache, const float* __restrict__ v_cache,
    const int* __restrict__ pos_ids, const int* __restrict__ block_offsets)
{
    extern __shared__ char smc[];
    uint32_t smb = smem_u32(smc);
    float* s_s   = (float*)(smc + ASS);
    float* row_m = (float*)(smc + AST);
    float* row_l = row_m + 64;
    float* row_c = row_l + 64;
    int*   pos_s = (int*)(row_c + 64);

    int n = blockIdx.x, b = blockIdx.y;
    int tid = threadIdx.x, lane = tid & 31, wid = tid >> 5;
    int wm = wid & 3, wn = wid >> 2;

    int ldrow = tid >> 5, ldq = tid & 31;
    int ldoff = ldrow * 256 + (((ldq >> 1) ^ (ldrow & 7)) << 4) + (ldq & 1) * 8;

    const float* qbase = g_qkv + (size_t)b * S_ * QKVW + (size_t)n * D_;
    {
        const float* kb; size_t kstr;
        kv_src(0, b, n, k_cache, block_offsets, HID_, kb, kstr);
#pragma unroll
        for (int i = 0; i < 4; i++) {
            int row = ldrow + i * 16;
            int off = ldoff + i * 16 * 256;
            float4 v = *(const float4*)(qbase + (size_t)row * QKVW + ldq * 4);
            uint32_t h[2], l[2];
            split4(v, h, l);
            *(uint2*)(smc + AQH + off) = make_uint2(h[0], h[1]);
            *(uint2*)(smc + AQL + off) = make_uint2(l[0], l[1]);
            float4 w = *(const float4*)(kb + (size_t)row * kstr + ldq * 4);
            split4(w, h, l);
            *(uint2*)(smc + AKH + off) = make_uint2(h[0], h[1]);
            *(uint2*)(smc + AKL + off) = make_uint2(l[0], l[1]);
        }
    }
    if (tid < 64) {
        row_m[tid] = -3.0e38f;
        row_l[tid] = 0.f;
        pos_s[tid] = pos_ids[b * S_ + tid];
    }
    __syncthreads();

    float accO[4][4];
#pragma unroll
    for (int i = 0; i < 4; i++)
#pragma unroll
        for (int e = 0; e < 4; e++) accO[i][e] = 0.f;

    const float scale = 0.08838834764831845f;

    int arow  = wm * 16 + ((lane >> 3) & 1) * 8 + (lane & 7);
    int nbRow = wn * 16 + ((lane >> 4) & 1) * 8 + (lane & 7);
    int prow  = arow;
    int vkeyb = ((lane >> 3) & 1) * 8 + (lane & 7);
    int achq  = (lane >> 4) & 1;
    int bchq  = (lane >> 3) & 1;

    for (int t = 0; t < 33; t++) {
        // ===== phase A: V-load(t) || QK MMA =====
        const float* vb; size_t vstr;
        kv_src(t, b, n, v_cache, block_offsets, 2 * HID_, vb, vstr);
        float4 vv[4];
#pragma unroll
        for (int i = 0; i < 4; i++)
            vv[i] = *(const float4*)(vb + (size_t)(ldrow + i * 16) * vstr + ldq * 4);

        float accs[2][4];
#pragma unroll
        for (int i = 0; i < 2; i++)
#pragma unroll
            for (int e = 0; e < 4; e++) accs[i][e] = 0.f;

#pragma unroll
        for (int ks = 0; ks < 8; ks++) {
            uint32_t ah[4], al[4];
            uint32_t aaddr = smb + AQH + arow * 256
                           + (((2 * ks + achq) ^ (arow & 7)) << 4);
            ldsm4(ah, aaddr);
            ldsm4(al, aaddr + (AQL - AQH));
            uint32_t bh[2][2], bl[2][2];
            {
                uint32_t baddr = smb + AKH + nbRow * 256
                               + (((2 * ks + bchq) ^ (nbRow & 7)) << 4);
                uint32_t r[4];
                ldsm4(r, baddr);
                bh[0][0] = r[0]; bh[0][1] = r[1];
                bh[1][0] = r[2]; bh[1][1] = r[3];
                ldsm4(r, baddr + (AKL - AKH));
                bl[0][0] = r[0]; bl[0][1] = r[1];
                bl[1][0] = r[2]; bl[1][1] = r[3];
            }
#pragma unroll
            for (int nt = 0; nt < 2; nt++) mma16816(accs[nt], ah, bh[nt]);
#pragma unroll
            for (int nt = 0; nt < 2; nt++) mma16816(accs[nt], ah, bl[nt]);
#pragma unroll
            for (int nt = 0; nt < 2; nt++) mma16816(accs[nt], al, bh[nt]);
        }
#pragma unroll
        for (int i = 0; i < 4; i++) {
            int off = ldoff + i * 16 * 256;
            uint32_t h[2], l[2];
            split4(vv[i], h, l);
            *(uint2*)(smc + AVH + off) = make_uint2(h[0], h[1]);
            *(uint2*)(smc + AVL + off) = make_uint2(l[0], l[1]);
        }
        {
            int r0 = wm * 16 + (lane >> 2);
            int c0 = wn * 16 + (lane & 3) * 2;
#pragma unroll
            for (int nt = 0; nt < 2; nt++) {
                *(float2*)&s_s[r0 * 68 + c0 + nt * 8] =
                    make_float2(accs[nt][0] * scale, accs[nt][1] * scale);
                *(float2*)&s_s[(r0 + 8) * 68 + c0 + nt * 8] =
                    make_float2(accs[nt][2] * scale, accs[nt][3] * scale);
            }
        }
        __syncthreads();

        // ===== phase B: online softmax (8 threads/row) =====
        {
            int r = tid >> 3, u = tid & 7;
            int lb = t * 64, pr = pos_s[r];
            bool nm = (lb + 63 > pr);
            float p8[8];
            float mloc = -3.0e38f;
#pragma unroll
            for (int jj = 0; jj < 8; jj++) {
                int j = u * 8 + jj;
                float sv = s_s[r * 68 + j];
                p8[jj] = sv;
                if (!nm || lb + j <= pr) mloc = fmaxf(mloc, sv);
            }
            mloc = fmaxf(mloc, __shfl_xor_sync(0xffffffffu, mloc, 1));
            mloc = fmaxf(mloc, __shfl_xor_sync(0xffffffffu, mloc, 2));
            mloc = fmaxf(mloc, __shfl_xor_sync(0xffffffffu, mloc, 4));
            float mnew = fmaxf(row_m[r], mloc);
            float sum = 0.f;
#pragma unroll
            for (int jj = 0; jj < 8; jj++) {
                int j = u * 8 + jj;
                float pv = 0.f;
                if (!nm || lb + j <= pr) pv = expf(p8[jj] - mnew);
                p8[jj] = pv;
                sum += pv;
            }
            sum += __shfl_xor_sync(0xffffffffu, sum, 1);
            sum += __shfl_xor_sync(0xffffffffu, sum, 2);
            sum += __shfl_xor_sync(0xffffffffu, sum, 4);
            {
                uint32_t hw[4], lw[4];
#pragma unroll
                for (int qd = 0; qd < 4; qd++) {
                    float x0 = p8[qd * 2], x1 = p8[qd * 2 + 1];
                    hw[qd] = pack_bf2(x0, x1);
                    float2 f = unpack_bf2(hw[qd]);
                    lw[qd] = pack_bf2(x0 - f.x, x1 - f.y);
                }
                int off = r * 128 + ((u ^ (r & 7)) << 4);
                *(uint4*)(smc + APH + off) = make_uint4(hw[0], hw[1], hw[2], hw[3]);
                *(uint4*)(smc + APL + off) = make_uint4(lw[0], lw[1], lw[2], lw[3]);
            }
            if (u == 0) {
                float corr = expf(row_m[r] - mnew);
                row_c[r] = corr;
                row_l[r] = row_l[r] * corr + sum;
                row_m[r] = mnew;
            }
        }
        __syncthreads();

        // ===== phase C: K(t+1)-load || PV MMA =====
        {
            int tn = t + 1 < 33 ? t + 1 : 32;
            const float* kb; size_t kstr;
            kv_src(tn, b, n, k_cache, block_offsets, HID_, kb, kstr);
            float4 kk[4];
#pragma unroll
            for (int i = 0; i < 4; i++)
                kk[i] = *(const float4*)(kb + (size_t)(ldrow + i * 16) * kstr + ldq * 4);

            float c0f = row_c[wm * 16 + (lane >> 2)];
            float c1f = row_c[wm * 16 + (lane >> 2) + 8];
#pragma unroll
            for (int nt = 0; nt < 4; nt++) {
                accO[nt][0] *= c0f; accO[nt][1] *= c0f;
                accO[nt][2] *= c1f; accO[nt][3] *= c1f;
            }
            uint32_t ph[4], pl[4];
#pragma unroll
            for (int idx = 0; idx < 8; idx++) {
                int ks = idx >> 1, pr2 = idx & 1;
                if (pr2 == 0) {
                    uint32_t paddr = smb + APH + prow * 128
                                   + (((2 * ks + achq) ^ (prow & 7)) << 4);
                    ldsm4(ph, paddr);
                    ldsm4(pl, paddr + (APL - APH));
                }
                int key = ks * 16 + vkeyb;
                int dch = wn * 4 + pr2 * 2 + achq;
                uint32_t vaddr = smb + AVH + key * 256
                               + ((dch ^ (key & 7)) << 4);
                uint32_t rh[4], rl[4];
                ldsm4t(rh, vaddr);
                ldsm4t(rl, vaddr + (AVL - AVH));
                uint32_t bh0[2] = { rh[0], rh[1] }, bh1[2] = { rh[2], rh[3] };
                uint32_t bl0[2] = { rl[0], rl[1] }, bl1[2] = { rl[2], rl[3] };
                mma16816(accO[pr2 * 2],     ph, bh0);
                mma16816(accO[pr2 * 2 + 1], ph, bh1);
                mma16816(accO[pr2 * 2],     ph, bl0);
                mma16816(accO[pr2 * 2 + 1], ph, bl1);
                mma16816(accO[pr2 * 2],     pl, bh0);
                mma16816(accO[pr2 * 2 + 1], pl, bh1);
            }
#pragma unroll
            for (int i = 0; i < 4; i++) {
                int off = ldoff + i * 16 * 256;
                uint32_t h[2], l[2];
                split4(kk[i], h, l);
                *(uint2*)(smc + AKH + off) = make_uint2(h[0], h[1]);
                *(uint2*)(smc + AKL + off) = make_uint2(l[0], l[1]);
            }
        }
        __syncthreads();
    }

    // ---- epilogue ----
    int r0 = wm * 16 + (lane >> 2);
    float il0 = 1.0f / row_l[r0];
    float il1 = 1.0f / row_l[r0 + 8];
    float* ob0 = g_attn + (size_t)(b * S_ + r0) * HID_ + (size_t)n * D_
               + wn * 32 + (lane & 3) * 2;
    float* ob1 = ob0 + 8 * HID_;
#pragma unroll
    for (int nt = 0; nt < 4; nt++) {
        *(float2*)(ob0 + nt * 8) = make_float2(accO[nt][0] * il0, accO[nt][1] * il0);
        *(float2*)(ob1 + nt * 8) = make_float2(accO[nt][2] * il1, accO[nt][3] * il1);
    }
}

// ------------------------------------------------------------------
// Launch
// ------------------------------------------------------------------
extern "C" void kernel_launch(void* const* d_in, const int* in_sizes, int n_in,
                              void* d_out, int out_size)
{
    const float* X  = (const float*)d_in[0];
    const float* kc = (const float*)d_in[1];
    const float* vc = (const float*)d_in[2];
    const float* wq = (const float*)d_in[3];
    const float* wk = (const float*)d_in[4];
    const float* wv = (const float*)d_in[5];
    const float* wo = (const float*)d_in[6];
    const int* pos  = (const int*)d_in[7];
    const int* bo   = (const int*)d_in[8];
    float* out = (float*)d_out;

    float *qkv_p, *attn_p;
    char *xt_p;
    cudaGetSymbolAddress((void**)&qkv_p, g_qkv);
    cudaGetSymbolAddress((void**)&attn_p, g_attn);
    cudaGetSymbolAddress((void**)&xt_p, g_xt);

    cudaFuncSetAttribute(gemm_ws, cudaFuncAttributeMaxDynamicSharedMemorySize,
                         GSMEM);
    cudaFuncSetAttribute(attn_tc, cudaFuncAttributeMaxDynamicSharedMemorySize,
                         ATTN_SMEM);

    // 0) convert X to bf16 hi/lo tiles
    conv_a<<<1024, 256>>>(X, xt_p);

    // 1) fused QKV projection (warp-specialized, 384 thr)
    gemm_ws<<<dim3(96, 4), 384, GSMEM>>>(xt_p, wq, wk, wv, qkv_p, HID_, QKVW);

    // 2) RoPE on q and k
    rope_k<<<(T_ * 64 * 64) / 256, 256>>>(pos);

    // 3) paged causal flash attention (512 thr, 16 warps)
    attn_tc<<<dim3(NH_, B_), 512, ATTN_SMEM>>>(kc, vc, pos, bo);

    // 4) convert attention output + output projection
    conv_a<<<1024, 256>>>(attn_p, xt_p);
    gemm_ws<<<dim3(32, 4), 384, GSMEM>>>(xt_p, wo, wo, wo, out, HID_, HID_);
}